// round 6
// baseline (speedup 1.0000x reference)
#include <cuda_runtime.h>
#include <cstdint>

// Problem constants: B=16384, F=16, V=300000, D=10
#define BSZ   16384
#define FDIM  16
#define VDIM  300000
#define DDIM  10
#define NPAIR 120                 // F*(F-1)/2
#define OUTW  1376                // 120*10 + 16*10 + 16
#define OUTW4 (OUTW / 4)          // 344

// L2-only loads (skip L1 fill — gathers have ~0 L1 hit rate).
__device__ __forceinline__ float4 ldcg_f4(const float4* p) { return __ldcg(p); }
__device__ __forceinline__ float2 ldcg_f2(const float2* p) { return __ldcg(p); }

__global__ __launch_bounds__(256, 8)
void feature_interact_kernel(const int*   __restrict__ x,    // [B, F]
                             const float* __restrict__ emb,  // [F, V, D]
                             const float* __restrict__ lin,  // [V, 1]
                             float*       __restrict__ out)  // [B, OUTW]
{
    __shared__ float E[FDIM * FDIM * DDIM];      // E[f][g][d] = emb[g, x[b,f]][d]
    __shared__ float lin_s[FDIM];
    __shared__ unsigned char pi_s[NPAIR], pj_s[NPAIR];

    const int b = blockIdx.x;
    const int t = threadIdx.x;

    // lin gather, once per block (hidden under the big gathers).
    if (t < FDIM) {
        lin_s[t] = __ldg(&lin[__ldg(&x[b * FDIM + t])]);
    }

    // triu(k=1) pair table.
    if (t < NPAIR) {
        int rem = t, i = 0;
        while (rem >= (FDIM - 1) - i) { rem -= (FDIM - 1) - i; ++i; }
        pi_s[t] = (unsigned char)i;
        pj_s[t] = (unsigned char)(i + 1 + rem);
    }

    // Gather phase: thread t owns (f = t>>4, g = t&15). 40B vector in 3 loads.
    {
        const int f = t >> 4;
        const int g = t & (FDIM - 1);
        const int idx = __ldg(&x[b * FDIM + f]);
        const float* base = emb + ((size_t)g * VDIM + (size_t)idx) * DDIM;

        float v[10];
        if ((((uintptr_t)base) & 15) == 0) {
            // 16B-aligned: f4 @0, f4 @16, f2 @32
            float4 a = ldcg_f4(reinterpret_cast<const float4*>(base));
            float4 c = ldcg_f4(reinterpret_cast<const float4*>(base + 4));
            float2 e = ldcg_f2(reinterpret_cast<const float2*>(base + 8));
            v[0]=a.x; v[1]=a.y; v[2]=a.z; v[3]=a.w;
            v[4]=c.x; v[5]=c.y; v[6]=c.z; v[7]=c.w;
            v[8]=e.x; v[9]=e.y;
        } else {
            // 8B-aligned: f2 @0, f4 @8, f4 @24 (both f4 are 16B-aligned)
            float2 a = ldcg_f2(reinterpret_cast<const float2*>(base));
            float4 c = ldcg_f4(reinterpret_cast<const float4*>(base + 2));
            float4 e = ldcg_f4(reinterpret_cast<const float4*>(base + 6));
            v[0]=a.x; v[1]=a.y;
            v[2]=c.x; v[3]=c.y; v[4]=c.z; v[5]=c.w;
            v[6]=e.x; v[7]=e.y; v[8]=e.z; v[9]=e.w;
        }

        float2* dst = reinterpret_cast<float2*>(E + t * DDIM);  // 8B-aligned (t*40)
        #pragma unroll
        for (int k = 0; k < 5; ++k) dst[k] = make_float2(v[2*k], v[2*k+1]);
    }
    __syncthreads();

    // Output phase: 344 float4 streaming stores per row (write-once data).
    float4* orow4 = reinterpret_cast<float4*>(out + (size_t)b * OUTW);
    #pragma unroll
    for (int q0 = 0; q0 < OUTW4; q0 += 256) {
        const int q = q0 + t;
        if (q0 + 256 <= OUTW4 || q < OUTW4) {
            float r[4];
            #pragma unroll
            for (int e = 0; e < 4; ++e) {
                const int k = q * 4 + e;
                float vv;
                if (k < NPAIR * DDIM) {
                    int p = k / DDIM, d = k - p * DDIM;
                    int i = pi_s[p], j = pj_s[p];
                    vv = E[(i * FDIM + j) * DDIM + d] * E[(j * FDIM + i) * DDIM + d];
                } else if (k < NPAIR * DDIM + FDIM * DDIM) {
                    int k2 = k - NPAIR * DDIM;
                    int f = k2 / DDIM, d = k2 - f * DDIM;
                    vv = E[(f * FDIM + f) * DDIM + d];
                } else {
                    vv = lin_s[k - (NPAIR * DDIM + FDIM * DDIM)];
                }
                r[e] = vv;
            }
            __stcs(&orow4[q], make_float4(r[0], r[1], r[2], r[3]));
        }
    }
}

extern "C" void kernel_launch(void* const* d_in, const int* in_sizes, int n_in,
                              void* d_out, int out_size)
{
    const int*   x   = nullptr;
    const float* emb = nullptr;
    const float* lin = nullptr;
    for (int i = 0; i < n_in; ++i) {
        if      (in_sizes[i] == BSZ * FDIM)          x   = (const int*)d_in[i];
        else if (in_sizes[i] == FDIM * VDIM * DDIM)  emb = (const float*)d_in[i];
        else if (in_sizes[i] == VDIM)                lin = (const float*)d_in[i];
    }
    feature_interact_kernel<<<BSZ, 256>>>(x, emb, lin, (float*)d_out);
}

// round 7
// speedup vs baseline: 1.0908x; 1.0908x over previous
#include <cuda_runtime.h>
#include <cstdint>

// Problem constants: B=16384, F=16, V=300000, D=10
#define BSZ   16384
#define FDIM  16
#define VDIM  300000
#define DDIM  10
#define NPAIR 120                 // F*(F-1)/2
#define OUTW  1376                // 120*10 + 16*10 + 16
#define OUTW4 (OUTW / 4)          // 344

__global__ __launch_bounds__(256, 8)
void feature_interact_kernel(const int*   __restrict__ x,    // [B, F]
                             const float* __restrict__ emb,  // [F, V, D]
                             const float* __restrict__ lin,  // [V, 1]
                             float*       __restrict__ out)  // [B, OUTW]
{
    __shared__ float E[FDIM * FDIM * DDIM];      // E[f][g][d] = emb[g, x[b,f]][d]
    __shared__ float lin_s[FDIM];
    __shared__ unsigned char pi_s[NPAIR], pj_s[NPAIR];

    const int b = blockIdx.x;
    const int t = threadIdx.x;

    // lin gather, once per block (hidden under the big gathers).
    if (t < FDIM) {
        lin_s[t] = __ldg(&lin[__ldg(&x[b * FDIM + t])]);
    }

    // triu(k=1) pair table.
    if (t < NPAIR) {
        int rem = t, i = 0;
        while (rem >= (FDIM - 1) - i) { rem -= (FDIM - 1) - i; ++i; }
        pi_s[t] = (unsigned char)i;
        pj_s[t] = (unsigned char)(i + 1 + rem);
    }

    // Gather phase: thread t owns (f = t>>4, g = t&15). 40B vector in 3 loads.
    // __ldg (L1-caching) is load-bearing here: table rows have ~1.5x fetch
    // multiplicity and L1 captures part of it (R6 showed .cg loses ~8%).
    {
        const int f = t >> 4;
        const int g = t & (FDIM - 1);
        const int idx = __ldg(&x[b * FDIM + f]);
        const float* base = emb + ((size_t)g * VDIM + (size_t)idx) * DDIM;

        float v[10];
        if ((((uintptr_t)base) & 15) == 0) {
            // 16B-aligned: f4 @0, f4 @16, f2 @32
            float4 a = __ldg(reinterpret_cast<const float4*>(base));
            float4 c = __ldg(reinterpret_cast<const float4*>(base + 4));
            float2 e = __ldg(reinterpret_cast<const float2*>(base + 8));
            v[0]=a.x; v[1]=a.y; v[2]=a.z; v[3]=a.w;
            v[4]=c.x; v[5]=c.y; v[6]=c.z; v[7]=c.w;
            v[8]=e.x; v[9]=e.y;
        } else {
            // 8B-aligned: f2 @0, f4 @8, f4 @24 (both f4 are 16B-aligned)
            float2 a = __ldg(reinterpret_cast<const float2*>(base));
            float4 c = __ldg(reinterpret_cast<const float4*>(base + 2));
            float4 e = __ldg(reinterpret_cast<const float4*>(base + 6));
            v[0]=a.x; v[1]=a.y;
            v[2]=c.x; v[3]=c.y; v[4]=c.z; v[5]=c.w;
            v[6]=e.x; v[7]=e.y; v[8]=e.z; v[9]=e.w;
        }

        float2* dst = reinterpret_cast<float2*>(E + t * DDIM);  // 8B-aligned (t*40)
        #pragma unroll
        for (int k = 0; k < 5; ++k) dst[k] = make_float2(v[2*k], v[2*k+1]);
    }
    __syncthreads();

    // Output phase: 344 float4 stores per row. Streaming (.cs): output is
    // write-once; evict-stream keeps L2 capacity for gather-row reuse.
    float4* orow4 = reinterpret_cast<float4*>(out + (size_t)b * OUTW);
    for (int q = t; q < OUTW4; q += 256) {
        float r[4];
        #pragma unroll
        for (int e = 0; e < 4; ++e) {
            const int k = q * 4 + e;
            float vv;
            if (k < NPAIR * DDIM) {
                int p = k / DDIM, d = k - p * DDIM;
                int i = pi_s[p], j = pj_s[p];
                vv = E[(i * FDIM + j) * DDIM + d] * E[(j * FDIM + i) * DDIM + d];
            } else if (k < NPAIR * DDIM + FDIM * DDIM) {
                int k2 = k - NPAIR * DDIM;
                int f = k2 / DDIM, d = k2 - f * DDIM;
                vv = E[(f * FDIM + f) * DDIM + d];
            } else {
                vv = lin_s[k - (NPAIR * DDIM + FDIM * DDIM)];
            }
            r[e] = vv;
        }
        __stcs(&orow4[q], make_float4(r[0], r[1], r[2], r[3]));
    }
}

extern "C" void kernel_launch(void* const* d_in, const int* in_sizes, int n_in,
                              void* d_out, int out_size)
{
    const int*   x   = nullptr;
    const float* emb = nullptr;
    const float* lin = nullptr;
    for (int i = 0; i < n_in; ++i) {
        if      (in_sizes[i] == BSZ * FDIM)          x   = (const int*)d_in[i];
        else if (in_sizes[i] == FDIM * VDIM * DDIM)  emb = (const float*)d_in[i];
        else if (in_sizes[i] == VDIM)                lin = (const float*)d_in[i];
    }
    feature_interact_kernel<<<BSZ, 256>>>(x, emb, lin, (float*)d_out);
}

// round 9
// speedup vs baseline: 1.1085x; 1.0162x over previous
#include <cuda_runtime.h>
#include <cstdint>

// Problem constants: B=16384, F=16, V=300000, D=10
#define BSZ   16384
#define FDIM  16
#define VDIM  300000
#define DDIM  10
#define NPAIR 120                 // F*(F-1)/2
#define OUTW  1376                // 120*10 + 16*10 + 16
#define OUTW4 (OUTW / 4)          // 344

// L2 retention policy: emb lines are the only data with forward reuse
// (~1.5x multiplicity), so bias L2 to keep them (evict_last) against the
// streaming output traffic. v2/v4 loads need the createpolicy/cache_hint form.
__device__ __forceinline__ uint64_t mk_evict_last_policy() {
    uint64_t p;
    asm("createpolicy.fractional.L2::evict_last.b64 %0, 1.0;" : "=l"(p));
    return p;
}
__device__ __forceinline__ float4 ldg_el_f4(const float* p, uint64_t pol) {
    float4 r;
    asm("ld.global.nc.L2::cache_hint.v4.f32 {%0,%1,%2,%3}, [%4], %5;"
        : "=f"(r.x), "=f"(r.y), "=f"(r.z), "=f"(r.w) : "l"(p), "l"(pol));
    return r;
}
__device__ __forceinline__ float2 ldg_el_f2(const float* p, uint64_t pol) {
    float2 r;
    asm("ld.global.nc.L2::cache_hint.v2.f32 {%0,%1}, [%2], %3;"
        : "=f"(r.x), "=f"(r.y) : "l"(p), "l"(pol));
    return r;
}

__global__ __launch_bounds__(256, 8)
void feature_interact_kernel(const int*   __restrict__ x,    // [B, F]
                             const float* __restrict__ emb,  // [F, V, D]
                             const float* __restrict__ lin,  // [V, 1]
                             float*       __restrict__ out)  // [B, OUTW]
{
    __shared__ float E[FDIM * FDIM * DDIM];      // E[f][g][d] = emb[g, x[b,f]][d]
    __shared__ float lin_s[FDIM];
    __shared__ unsigned char pi_s[NPAIR], pj_s[NPAIR];

    const int b = blockIdx.x;
    const int t = threadIdx.x;

    // lin gather, once per block (hidden under the big gathers).
    if (t < FDIM) {
        lin_s[t] = __ldg(&lin[__ldg(&x[b * FDIM + t])]);
    }

    // triu(k=1) pair table.
    if (t < NPAIR) {
        int rem = t, i = 0;
        while (rem >= (FDIM - 1) - i) { rem -= (FDIM - 1) - i; ++i; }
        pi_s[t] = (unsigned char)i;
        pj_s[t] = (unsigned char)(i + 1 + rem);
    }

    // Gather phase: thread t owns (f = t>>4, g = t&15). 40B vector in 3 loads.
    // L1-cached (load-bearing per R6), L2 evict_last via cache-hint policy.
    {
        const int f = t >> 4;
        const int g = t & (FDIM - 1);
        const int idx = __ldg(&x[b * FDIM + f]);
        const float* base = emb + ((size_t)g * VDIM + (size_t)idx) * DDIM;
        const uint64_t pol = mk_evict_last_policy();

        float v[10];
        if ((((uintptr_t)base) & 15) == 0) {
            // 16B-aligned: f4 @0, f4 @16, f2 @32
            float4 a = ldg_el_f4(base, pol);
            float4 c = ldg_el_f4(base + 4, pol);
            float2 e = ldg_el_f2(base + 8, pol);
            v[0]=a.x; v[1]=a.y; v[2]=a.z; v[3]=a.w;
            v[4]=c.x; v[5]=c.y; v[6]=c.z; v[7]=c.w;
            v[8]=e.x; v[9]=e.y;
        } else {
            // 8B-aligned: f2 @0, f4 @8, f4 @24 (both f4 are 16B-aligned)
            float2 a = ldg_el_f2(base, pol);
            float4 c = ldg_el_f4(base + 2, pol);
            float4 e = ldg_el_f4(base + 6, pol);
            v[0]=a.x; v[1]=a.y;
            v[2]=c.x; v[3]=c.y; v[4]=c.z; v[5]=c.w;
            v[6]=e.x; v[7]=e.y; v[8]=e.z; v[9]=e.w;
        }

        float2* dst = reinterpret_cast<float2*>(E + t * DDIM);  // 8B-aligned (t*40)
        #pragma unroll
        for (int k = 0; k < 5; ++k) dst[k] = make_float2(v[2*k], v[2*k+1]);
    }
    __syncthreads();

    // Output phase: 344 float4 streaming stores per row (write-once data,
    // evict-stream keeps L2 capacity for gather reuse).
    float4* orow4 = reinterpret_cast<float4*>(out + (size_t)b * OUTW);
    for (int q = t; q < OUTW4; q += 256) {
        float r[4];
        #pragma unroll
        for (int e = 0; e < 4; ++e) {
            const int k = q * 4 + e;
            float vv;
            if (k < NPAIR * DDIM) {
                int p = k / DDIM, d = k - p * DDIM;
                int i = pi_s[p], j = pj_s[p];
                vv = E[(i * FDIM + j) * DDIM + d] * E[(j * FDIM + i) * DDIM + d];
            } else if (k < NPAIR * DDIM + FDIM * DDIM) {
                int k2 = k - NPAIR * DDIM;
                int f = k2 / DDIM, d = k2 - f * DDIM;
                vv = E[(f * FDIM + f) * DDIM + d];
            } else {
                vv = lin_s[k - (NPAIR * DDIM + FDIM * DDIM)];
            }
            r[e] = vv;
        }
        __stcs(&orow4[q], make_float4(r[0], r[1], r[2], r[3]));
    }
}

extern "C" void kernel_launch(void* const* d_in, const int* in_sizes, int n_in,
                              void* d_out, int out_size)
{
    const int*   x   = nullptr;
    const float* emb = nullptr;
    const float* lin = nullptr;
    for (int i = 0; i < n_in; ++i) {
        if      (in_sizes[i] == BSZ * FDIM)          x   = (const int*)d_in[i];
        else if (in_sizes[i] == FDIM * VDIM * DDIM)  emb = (const float*)d_in[i];
        else if (in_sizes[i] == VDIM)                lin = (const float*)d_in[i];
    }
    feature_interact_kernel<<<BSZ, 256>>>(x, emb, lin, (float*)d_out);
}